// round 1
// baseline (speedup 1.0000x reference)
#include <cuda_runtime.h>
#include <cuda_bf16.h>
#include <math.h>

// Problem constants
#define BB 4
#define SS 512
#define DD 1024
#define HH 16
#define DHH 64
#define DFF 4096
#define LL 6

#define MTOK (BB*SS)          // 2048 token rows

// ---------------- device scratch (no allocation allowed) ----------------
__device__ float g_x [MTOK*DD];
__device__ float g_q [MTOK*DD];
__device__ float g_k [MTOK*DD];
__device__ float g_v [MTOK*DD];
__device__ float g_av[MTOK*DD];
__device__ float g_y [MTOK*DD];
__device__ float g_x1[MTOK*DD];
__device__ float g_ff[MTOK*DFF];

// ---------------- embedding: x = word_emb[tok] + pos_table[tok] ----------------
__global__ void embed_kernel(const int* __restrict__ tok,
                             const float* __restrict__ we,
                             const float* __restrict__ pt,
                             float* __restrict__ x)
{
    int m = blockIdx.x;                 // 0..2047
    int t = tok[m];
    const float* wr = we + (size_t)t * DD;
    const float* pr = pt + (size_t)t * DD;
    float* xr = x + (size_t)m * DD;
    for (int j = threadIdx.x; j < DD; j += blockDim.x)
        xr[j] = wr[j] + pr[j];
}

// ---------------- generic tiled SGEMM, C = A[MxK] * B[KxN] + bias, epilogues ----
// mode 0: plain+bias   mode 1: relu(.)   mode 2: + residual   mode 3: QKV remap
#define BM 64
#define BN 64
#define BKg 16

__global__ __launch_bounds__(256)
void gemm_kernel(const float* __restrict__ A, const float* __restrict__ Bm,
                 const float* __restrict__ bias, const float* __restrict__ Res,
                 float* __restrict__ C, int M, int N, int K, int mode)
{
    __shared__ float As[BM][BKg + 1];
    __shared__ float Bs[BKg][BN];

    int tid = threadIdx.x;
    int bm = blockIdx.y, bn = blockIdx.x;
    int ty = tid >> 4, tx = tid & 15;

    float acc[4][4] = {};

    const float* Ab = A + (size_t)(bm * BM) * K;
    const float* Bb = Bm + bn * BN;

    for (int k0 = 0; k0 < K; k0 += BKg) {
        #pragma unroll
        for (int i = 0; i < 4; i++) {
            int idx = tid + i * 256;
            int r = idx >> 4, c = idx & 15;
            As[r][c] = Ab[(size_t)r * K + k0 + c];
        }
        #pragma unroll
        for (int i = 0; i < 4; i++) {
            int idx = tid + i * 256;
            int r = idx >> 6, c = idx & 63;
            Bs[r][c] = Bb[(size_t)(k0 + r) * N + c];
        }
        __syncthreads();

        #pragma unroll
        for (int kk = 0; kk < BKg; kk++) {
            float a[4], bb[4];
            #pragma unroll
            for (int i = 0; i < 4; i++) a[i] = As[ty * 4 + i][kk];
            #pragma unroll
            for (int j = 0; j < 4; j++) bb[j] = Bs[kk][tx * 4 + j];
            #pragma unroll
            for (int i = 0; i < 4; i++)
                #pragma unroll
                for (int j = 0; j < 4; j++)
                    acc[i][j] = fmaf(a[i], bb[j], acc[i][j]);
        }
        __syncthreads();
    }

    #pragma unroll
    for (int i = 0; i < 4; i++) {
        int m = bm * BM + ty * 4 + i;
        #pragma unroll
        for (int j = 0; j < 4; j++) {
            int n = bn * BN + tx * 4 + j;
            float val = acc[i][j] + bias[n];
            if (mode == 1) val = fmaxf(val, 0.f);
            else if (mode == 2) val += Res[(size_t)m * N + n];
            if (mode == 3) {
                // out[b][h][s][d] from m=b*512+s, n=h*64+d
                int b = m >> 9, s = m & 511, h = n >> 6, d = n & 63;
                C[((((size_t)b * HH + h) * SS + s) << 6) + d] = val;
            } else {
                C[(size_t)m * N + n] = val;
            }
        }
    }
}

// ---------------- fused attention: scores -> mask -> softmax -> probs out -> AV
// grid: (S/8, H, B), block 256.  q,k,v laid out [B,H,S,64].
__global__ __launch_bounds__(256)
void attn_kernel(const float* __restrict__ q, const float* __restrict__ k,
                 const float* __restrict__ v, const int* __restrict__ tok,
                 float* __restrict__ probs, float* __restrict__ av)
{
    int qb = blockIdx.x;               // query group of 8
    int h = blockIdx.y, b = blockIdx.z;
    int tid = threadIdx.x;

    __shared__ float qs[8][64];
    __shared__ float sc[8][512];

    const float* qbase = q + ((((size_t)b * HH + h) * SS + qb * 8) << 6);
    for (int i = tid; i < 8 * 64; i += 256)
        qs[i >> 6][i & 63] = qbase[i];
    __syncthreads();

    const float* kbase = k + (((size_t)b * HH + h) * SS << 6);
    const int* tb = tok + b * SS;

    // scores
    for (int idx = tid; idx < 8 * 512; idx += 256) {
        int qi = idx >> 9, key = idx & 511;
        const float4* kr4 = (const float4*)(kbase + ((size_t)key << 6));
        float acc = 0.f;
        #pragma unroll
        for (int d4 = 0; d4 < 16; d4++) {
            float4 kv = kr4[d4];
            acc = fmaf(qs[qi][4 * d4 + 0], kv.x, acc);
            acc = fmaf(qs[qi][4 * d4 + 1], kv.y, acc);
            acc = fmaf(qs[qi][4 * d4 + 2], kv.z, acc);
            acc = fmaf(qs[qi][4 * d4 + 3], kv.w, acc);
        }
        sc[qi][key] = (tb[key] == 0) ? -INFINITY : acc * 0.125f;
    }
    __syncthreads();

    // softmax: one warp per query row
    int w = tid >> 5, lane = tid & 31;
    {
        float m = -INFINITY;
        for (int key = lane; key < 512; key += 32) m = fmaxf(m, sc[w][key]);
        #pragma unroll
        for (int o = 16; o > 0; o >>= 1) m = fmaxf(m, __shfl_xor_sync(~0u, m, o));
        float sum = 0.f;
        for (int key = lane; key < 512; key += 32) {
            float e = __expf(sc[w][key] - m);
            sc[w][key] = e; sum += e;
        }
        #pragma unroll
        for (int o = 16; o > 0; o >>= 1) sum += __shfl_xor_sync(~0u, sum, o);
        float inv = 1.f / sum;
        float* prow = probs + ((((size_t)b * HH + h) * SS + qb * 8 + w) << 9);
        for (int key = lane; key < 512; key += 32) {
            float p = sc[w][key] * inv;
            sc[w][key] = p;
            prow[key] = p;
        }
    }
    __syncthreads();

    // AV: 64 threads per query, 2 passes
    const float* vbase = v + (((size_t)b * HH + h) * SS << 6);
    int d = tid & 63;
    #pragma unroll
    for (int pass = 0; pass < 2; pass++) {
        int qi = (tid >> 6) + pass * 4;
        float acc = 0.f;
        #pragma unroll 4
        for (int key = 0; key < 512; key++)
            acc = fmaf(sc[qi][key], vbase[((size_t)key << 6) + d], acc);
        // av laid out [B,S, H*64] for the O projection
        av[(((size_t)b * SS + qb * 8 + qi) << 10) + (h << 6) + d] = acc;
    }
}

// ---------------- layernorm over last dim (1024), weight=1 bias=0 ----------------
__global__ __launch_bounds__(256)
void ln_kernel(const float* __restrict__ in, float* __restrict__ out)
{
    int row = blockIdx.x;
    int tid = threadIdx.x;
    const float* r = in + (size_t)row * DD;
    float v0 = r[tid], v1 = r[tid + 256], v2 = r[tid + 512], v3 = r[tid + 768];
    float s = v0 + v1 + v2 + v3;

    __shared__ float sh[32];
    #pragma unroll
    for (int o = 16; o > 0; o >>= 1) s += __shfl_down_sync(~0u, s, o);
    if ((tid & 31) == 0) sh[tid >> 5] = s;
    __syncthreads();
    if (tid < 8) {
        s = sh[tid];
        #pragma unroll
        for (int o = 4; o > 0; o >>= 1) s += __shfl_down_sync(0xffu, s, o);
        if (tid == 0) sh[0] = s;
    }
    __syncthreads();
    float mean = sh[0] * (1.f / 1024.f);
    float d0 = v0 - mean, d1 = v1 - mean, d2 = v2 - mean, d3 = v3 - mean;
    float qv = d0 * d0 + d1 * d1 + d2 * d2 + d3 * d3;
    __syncthreads();
    #pragma unroll
    for (int o = 16; o > 0; o >>= 1) qv += __shfl_down_sync(~0u, qv, o);
    if ((tid & 31) == 0) sh[tid >> 5] = qv;
    __syncthreads();
    if (tid < 8) {
        qv = sh[tid];
        #pragma unroll
        for (int o = 4; o > 0; o >>= 1) qv += __shfl_down_sync(0xffu, qv, o);
        if (tid == 0) sh[0] = qv;
    }
    __syncthreads();
    float inv = rsqrtf(sh[0] * (1.f / 1024.f) + 1e-5f);
    float* o_ = out + (size_t)row * DD;
    o_[tid] = d0 * inv; o_[tid + 256] = d1 * inv;
    o_[tid + 512] = d2 * inv; o_[tid + 768] = d3 * inv;
}

// ---------------- final copy x -> out[0 : B*S*D] ----------------
__global__ void copy_kernel(const float* __restrict__ src, float* __restrict__ dst, int n)
{
    int i = blockIdx.x * blockDim.x + threadIdx.x;
    if (i < n) dst[i] = src[i];
}

// ---------------- host driver ----------------
extern "C" void kernel_launch(void* const* d_in, const int* in_sizes, int n_in,
                              void* d_out, int out_size)
{
    const int*   tok = (const int*)d_in[0];
    const float* we  = (const float*)d_in[1];
    const float* pt  = (const float*)d_in[2];
    const float* Wq  = (const float*)d_in[3];  const float* bq = (const float*)d_in[4];
    const float* Wk  = (const float*)d_in[5];  const float* bk = (const float*)d_in[6];
    const float* Wv  = (const float*)d_in[7];  const float* bv = (const float*)d_in[8];
    const float* Wo  = (const float*)d_in[9];  const float* bo = (const float*)d_in[10];
    const float* W1  = (const float*)d_in[11]; const float* b1 = (const float*)d_in[12];
    const float* W2  = (const float*)d_in[13]; const float* b2 = (const float*)d_in[14];
    float* out = (float*)d_out;

    float *x, *qp, *kp, *vp, *avp, *yp, *x1p, *ffp;
    cudaGetSymbolAddress((void**)&x,   g_x);
    cudaGetSymbolAddress((void**)&qp,  g_q);
    cudaGetSymbolAddress((void**)&kp,  g_k);
    cudaGetSymbolAddress((void**)&vp,  g_v);
    cudaGetSymbolAddress((void**)&avp, g_av);
    cudaGetSymbolAddress((void**)&yp,  g_y);
    cudaGetSymbolAddress((void**)&x1p, g_x1);
    cudaGetSymbolAddress((void**)&ffp, g_ff);

    embed_kernel<<<MTOK, 256>>>(tok, we, pt, x);

    const int M = MTOK;
    dim3 gD (DD  / BN, M / BM);   // N=1024
    dim3 gFF(DFF / BN, M / BM);   // N=4096
    dim3 gA (SS / 8, HH, BB);

    const size_t PROJ = (size_t)DD * (HH * DHH);   // 1024*1024
    const size_t W1SZ = (size_t)DD * DFF;
    const size_t W2SZ = (size_t)DFF * DD;
    const size_t CORR = (size_t)BB * HH * SS * SS; // per-layer probs

    for (int l = 0; l < LL; l++) {
        gemm_kernel<<<gD, 256>>>(x, Wq + l * PROJ, bq + l * DD, nullptr, qp, M, DD, DD, 3);
        gemm_kernel<<<gD, 256>>>(x, Wk + l * PROJ, bk + l * DD, nullptr, kp, M, DD, DD, 3);
        gemm_kernel<<<gD, 256>>>(x, Wv + l * PROJ, bv + l * DD, nullptr, vp, M, DD, DD, 3);

        float* probs_l = out + (size_t)MTOK * DD + (size_t)l * CORR;
        attn_kernel<<<gA, 256>>>(qp, kp, vp, tok, probs_l, avp);

        gemm_kernel<<<gD, 256>>>(avp, Wo + l * PROJ, bo + l * DD, x, yp, M, DD, DD, 2);
        ln_kernel<<<M, 256>>>(yp, x1p);

        gemm_kernel<<<gFF, 256>>>(x1p, W1 + l * W1SZ, b1 + l * DFF, nullptr, ffp, M, DFF, DD, 1);
        gemm_kernel<<<gD, 256>>>(ffp, W2 + l * W2SZ, b2 + l * DD, x1p, yp, M, DD, DFF, 2);
        ln_kernel<<<M, 256>>>(yp, x);
    }

    int n = MTOK * DD;
    copy_kernel<<<(n + 255) / 256, 256>>>(x, out, n);
}

// round 3
// speedup vs baseline: 1.7988x; 1.7988x over previous
#include <cuda_runtime.h>
#include <cuda_bf16.h>
#include <math.h>
#include <stdint.h>

// Problem constants
#define BB 4
#define SS 512
#define DD 1024
#define HH 16
#define DHH 64
#define DFF 4096
#define LL 6
#define MTOK (BB*SS)          // 2048 token rows

typedef __nv_bfloat16 bf16;

// ================= device scratch =================
__device__ float g_x  [MTOK*DD];    // residual stream fp32
__device__ bf16  g_xh [MTOK*DD],  g_xl [MTOK*DD];
__device__ float g_q  [MTOK*DD];
__device__ float g_k  [MTOK*DD];
__device__ float g_v  [MTOK*DD];
__device__ bf16  g_avh[MTOK*DD],  g_avl[MTOK*DD];
__device__ float g_y  [MTOK*DD];
__device__ float g_x1 [MTOK*DD];
__device__ bf16  g_x1h[MTOK*DD],  g_x1l[MTOK*DD];
__device__ bf16  g_ffh[MTOK*DFF], g_ffl[MTOK*DFF];

// transposed + bf16-split weights: [N, K] K-major per layer
__device__ bf16 g_wqT_h[LL*DD*DD],  g_wqT_l[LL*DD*DD];
__device__ bf16 g_wkT_h[LL*DD*DD],  g_wkT_l[LL*DD*DD];
__device__ bf16 g_wvT_h[LL*DD*DD],  g_wvT_l[LL*DD*DD];
__device__ bf16 g_woT_h[LL*DD*DD],  g_woT_l[LL*DD*DD];
__device__ bf16 g_w1T_h[LL*DD*DFF], g_w1T_l[LL*DD*DFF];
__device__ bf16 g_w2T_h[LL*DFF*DD], g_w2T_l[LL*DFF*DD];

// ================= small helpers =================
__device__ __forceinline__ uint32_t smem_u32(const void* p) {
    uint32_t a;
    asm("{ .reg .u64 t; cvta.to.shared.u64 t, %1; cvt.u32.u64 %0, t; }" : "=r"(a) : "l"(p));
    return a;
}
__device__ __forceinline__ void split_bf16(float v, bf16& h, bf16& l) {
    h = __float2bfloat16_rn(v);
    l = __float2bfloat16_rn(v - __bfloat162float(h));
}

#define CP_ASYNC16(sa, ga) \
    asm volatile("cp.async.cg.shared.global [%0], [%1], 16;" :: "r"(sa), "l"(ga) : "memory")
#define CP_COMMIT() asm volatile("cp.async.commit_group;" ::: "memory")
#define CP_WAIT1()  asm volatile("cp.async.wait_group 1;" ::: "memory")

#define LDSM_X4(r0,r1,r2,r3, addr) \
    asm volatile("ldmatrix.sync.aligned.m8n8.x4.shared.b16 {%0,%1,%2,%3}, [%4];" \
        : "=r"(r0), "=r"(r1), "=r"(r2), "=r"(r3) : "r"(addr))

#define MMA_BF16(d, a, b0, b1) \
    asm volatile("mma.sync.aligned.m16n8k16.row.col.f32.bf16.bf16.f32 " \
        "{%0,%1,%2,%3}, {%4,%5,%6,%7}, {%8,%9}, {%0,%1,%2,%3};" \
        : "+f"((d)[0]), "+f"((d)[1]), "+f"((d)[2]), "+f"((d)[3]) \
        : "r"((a)[0]), "r"((a)[1]), "r"((a)[2]), "r"((a)[3]), "r"(b0), "r"(b1))

// ================= embedding: x = we[tok] + pt[tok], plus bf16 split ========
__global__ void embed_kernel(const int* __restrict__ tok,
                             const float* __restrict__ we,
                             const float* __restrict__ pt,
                             float* __restrict__ x,
                             bf16* __restrict__ xh, bf16* __restrict__ xl)
{
    int m = blockIdx.x;
    int t = tok[m];
    const float* wr = we + (size_t)t * DD;
    const float* pr = pt + (size_t)t * DD;
    size_t base = (size_t)m * DD;
    for (int j = threadIdx.x; j < DD; j += blockDim.x) {
        float v = wr[j] + pr[j];
        x[base + j] = v;
        bf16 h, l; split_bf16(v, h, l);
        xh[base + j] = h; xl[base + j] = l;
    }
}

// ========== weight transpose + bf16 split: W[K,N] (fp32) -> Th/Tl [N,K] ======
__global__ __launch_bounds__(256)
void wsplit_kernel(const float* __restrict__ W, bf16* __restrict__ Th,
                   bf16* __restrict__ Tl, int K, int N)
{
    __shared__ float s[32][33];
    const float* Wb = W + (size_t)blockIdx.z * K * N;
    bf16* Thb = Th + (size_t)blockIdx.z * K * N;
    bf16* Tlb = Tl + (size_t)blockIdx.z * K * N;
    int nb = blockIdx.x * 32, kb = blockIdx.y * 32;
    int tx = threadIdx.x & 31, ty = threadIdx.x >> 5;
    #pragma unroll
    for (int j = 0; j < 4; j++)
        s[ty + 8*j][tx] = Wb[(size_t)(kb + ty + 8*j) * N + nb + tx];
    __syncthreads();
    #pragma unroll
    for (int j = 0; j < 4; j++) {
        float v = s[tx][ty + 8*j];
        bf16 h, l; split_bf16(v, h, l);
        size_t o = (size_t)(nb + ty + 8*j) * K + kb + tx;
        Thb[o] = h; Tlb[o] = l;
    }
}

// ================= bf16x3 mma.sync GEMM =================
// C[M=2048,N] = A * B^T; A given as bf16 h/l [M,K] row-major, B as bf16 h/l [N,K].
// D = AhBh + AlBh + AhBl.  Tile 128x128, BK=32, 3-stage cp.async pipeline.
// mode 0: fp32 C + bias; 1: relu -> bf16 h/l; 2: +bias+Res -> fp32; 3: QKV remap.
#define STAGE_B 32768                  // Ah(8K) Al(8K) Bh(8K) Bl(8K)
#define GSMEM (3*STAGE_B)

__global__ __launch_bounds__(256)
void gemm_kernel(const bf16* __restrict__ Ah, const bf16* __restrict__ Al,
                 const bf16* __restrict__ Bh, const bf16* __restrict__ Bl,
                 const float* __restrict__ bias, const float* __restrict__ Res,
                 float* __restrict__ C, bf16* __restrict__ Ch, bf16* __restrict__ Cl,
                 int K, int N, int mode)
{
    extern __shared__ char smem[];
    const uint32_t sb = smem_u32(smem);
    const int tid = threadIdx.x;
    const int lane = tid & 31, wid = tid >> 5;
    const int warp_m = wid & 3, warp_n = wid >> 2;
    const int m0 = blockIdx.y * 128, n0 = blockIdx.x * 128;

    // -------- loader mapping: 2 chunks per thread per tile --------
    // idx = tid + 256*j : row = idx>>2, kg = idx&3 (16B groups along K)
    int lrow0 = tid >> 2, lkg0 = tid & 3;
    int lrow1 = (tid + 256) >> 2, lkg1 = tid & 3;
    uint32_t soff0 = (uint32_t)(lrow0 * 64 + ((lkg0 ^ ((lrow0 >> 1) & 3)) << 4));
    uint32_t soff1 = (uint32_t)(lrow1 * 64 + ((lkg1 ^ ((lrow1 >> 1) & 3)) << 4));

    const bf16* gAh = Ah + (size_t)(m0 + lrow0) * K + lkg0 * 8;
    const bf16* gAl = Al + (size_t)(m0 + lrow0) * K + lkg0 * 8;
    const bf16* gBh = Bh + (size_t)(n0 + lrow0) * K + lkg0 * 8;
    const bf16* gBl = Bl + (size_t)(n0 + lrow0) * K + lkg0 * 8;
    const bf16* gAh1 = Ah + (size_t)(m0 + lrow1) * K + lkg1 * 8;
    const bf16* gAl1 = Al + (size_t)(m0 + lrow1) * K + lkg1 * 8;
    const bf16* gBh1 = Bh + (size_t)(n0 + lrow1) * K + lkg1 * 8;
    const bf16* gBl1 = Bl + (size_t)(n0 + lrow1) * K + lkg1 * 8;

    // -------- ldmatrix per-lane offsets --------
    // A tiles: x4 covers m16 x k16. lanes: mat = lane>>3
    //   row = mbase + (mat&1)*8 + (lane&7); kg = ks*2 + (mat>>1)
    int matA = lane >> 3;
    int arow_local = ((matA & 1) << 3) + (lane & 7);
    int akgbit = matA >> 1;
    uint32_t offA[2][2];
    #pragma unroll
    for (int mt = 0; mt < 2; mt++) {
        int row = warp_m * 32 + mt * 16 + arow_local;
        int swz = (row >> 1) & 3;
        #pragma unroll
        for (int ks = 0; ks < 2; ks++) {
            int kg = ks * 2 + akgbit;
            offA[mt][ks] = (uint32_t)(row * 64 + ((kg ^ swz) << 4));
        }
    }
    // B tiles: x4 covers n16 x k16. lanes: mat = lane>>3
    //   row = nbase + (mat>>1)*8 + (lane&7); kg = ks*2 + (mat&1)
    int matB = lane >> 3;
    int brow_local = ((matB >> 1) << 3) + (lane & 7);
    int bkgbit = matB & 1;
    uint32_t offB[4][2];
    #pragma unroll
    for (int np = 0; np < 4; np++) {
        int row = warp_n * 64 + np * 16 + brow_local;
        int swz = (row >> 1) & 3;
        #pragma unroll
        for (int ks = 0; ks < 2; ks++) {
            int kg = ks * 2 + bkgbit;
            offB[np][ks] = (uint32_t)(row * 64 + ((kg ^ swz) << 4));
        }
    }

    float acc[2][8][4];
    #pragma unroll
    for (int i = 0; i < 2; i++)
        #pragma unroll
        for (int j = 0; j < 8; j++)
            #pragma unroll
            for (int q = 0; q < 4; q++) acc[i][j][q] = 0.f;

    const int NC = K >> 5;

    // -------- load one stage --------
    auto load_stage = [&](int stage, int chunk) {
        uint32_t base = sb + stage * STAGE_B;
        size_t gk = (size_t)(chunk << 5);
        CP_ASYNC16(base           + soff0, gAh  + gk);
        CP_ASYNC16(base +  8192u  + soff0, gAl  + gk);
        CP_ASYNC16(base + 16384u  + soff0, gBh  + gk);
        CP_ASYNC16(base + 24576u  + soff0, gBl  + gk);
        CP_ASYNC16(base           + soff1, gAh1 + gk);
        CP_ASYNC16(base +  8192u  + soff1, gAl1 + gk);
        CP_ASYNC16(base + 16384u  + soff1, gBh1 + gk);
        CP_ASYNC16(base + 24576u  + soff1, gBl1 + gk);
    };

    load_stage(0, 0); CP_COMMIT();
    if (NC > 1) load_stage(1, 1);
    CP_COMMIT();

    for (int i = 0; i < NC; i++) {
        CP_WAIT1();
        __syncthreads();

        uint32_t base = sb + (i % 3) * STAGE_B;
        uint32_t sAh = base, sAl = base + 8192u, sBh = base + 16384u, sBl = base + 24576u;

        #pragma unroll
        for (int ks = 0; ks < 2; ks++) {
            uint32_t ah[2][4], al[2][4];
            #pragma unroll
            for (int mt = 0; mt < 2; mt++) {
                LDSM_X4(ah[mt][0], ah[mt][1], ah[mt][2], ah[mt][3], sAh + offA[mt][ks]);
                LDSM_X4(al[mt][0], al[mt][1], al[mt][2], al[mt][3], sAl + offA[mt][ks]);
            }
            #pragma unroll
            for (int np = 0; np < 4; np++) {
                uint32_t bh[4], bl[4];
                LDSM_X4(bh[0], bh[1], bh[2], bh[3], sBh + offB[np][ks]);
                LDSM_X4(bl[0], bl[1], bl[2], bl[3], sBl + offB[np][ks]);
                #pragma unroll
                for (int mt = 0; mt < 2; mt++) {
                    MMA_BF16(acc[mt][np*2+0], ah[mt], bh[0], bh[1]);
                    MMA_BF16(acc[mt][np*2+0], al[mt], bh[0], bh[1]);
                    MMA_BF16(acc[mt][np*2+0], ah[mt], bl[0], bl[1]);
                    MMA_BF16(acc[mt][np*2+1], ah[mt], bh[2], bh[3]);
                    MMA_BF16(acc[mt][np*2+1], al[mt], bh[2], bh[3]);
                    MMA_BF16(acc[mt][np*2+1], ah[mt], bl[2], bl[3]);
                }
            }
        }
        __syncthreads();
        if (i + 2 < NC) load_stage((i + 2) % 3, i + 2);
        CP_COMMIT();
    }

    // -------- epilogue --------
    #pragma unroll
    for (int mt = 0; mt < 2; mt++) {
        int r0 = m0 + warp_m * 32 + mt * 16 + (lane >> 2);
        int r1 = r0 + 8;
        #pragma unroll
        for (int nt = 0; nt < 8; nt++) {
            int c = n0 + warp_n * 64 + nt * 8 + ((lane & 3) << 1);
            float2 bv = *(const float2*)(bias + c);
            float v00 = acc[mt][nt][0] + bv.x, v01 = acc[mt][nt][1] + bv.y;
            float v10 = acc[mt][nt][2] + bv.x, v11 = acc[mt][nt][3] + bv.y;
            if (mode == 0) {
                *(float2*)(C + (size_t)r0 * N + c) = make_float2(v00, v01);
                *(float2*)(C + (size_t)r1 * N + c) = make_float2(v10, v11);
            } else if (mode == 1) {
                v00 = fmaxf(v00, 0.f); v01 = fmaxf(v01, 0.f);
                v10 = fmaxf(v10, 0.f); v11 = fmaxf(v11, 0.f);
                bf16 h0,l0,h1,l1,h2,l2,h3,l3;
                split_bf16(v00,h0,l0); split_bf16(v01,h1,l1);
                split_bf16(v10,h2,l2); split_bf16(v11,h3,l3);
                __nv_bfloat162 ph0; ph0.x = h0; ph0.y = h1;
                __nv_bfloat162 pl0; pl0.x = l0; pl0.y = l1;
                __nv_bfloat162 ph1; ph1.x = h2; ph1.y = h3;
                __nv_bfloat162 pl1; pl1.x = l2; pl1.y = l3;
                *(__nv_bfloat162*)(Ch + (size_t)r0 * N + c) = ph0;
                *(__nv_bfloat162*)(Cl + (size_t)r0 * N + c) = pl0;
                *(__nv_bfloat162*)(Ch + (size_t)r1 * N + c) = ph1;
                *(__nv_bfloat162*)(Cl + (size_t)r1 * N + c) = pl1;
            } else if (mode == 2) {
                float2 q0 = *(const float2*)(Res + (size_t)r0 * N + c);
                float2 q1 = *(const float2*)(Res + (size_t)r1 * N + c);
                *(float2*)(C + (size_t)r0 * N + c) = make_float2(v00 + q0.x, v01 + q0.y);
                *(float2*)(C + (size_t)r1 * N + c) = make_float2(v10 + q1.x, v11 + q1.y);
            } else {
                // QKV remap: m=(b,s), n=(h,d) -> [B,H,S,64]
                int b0_ = r0 >> 9, s0_ = r0 & 511;
                int b1_ = r1 >> 9, s1_ = r1 & 511;
                int h_ = c >> 6, d_ = c & 63;
                *(float2*)(C + ((((size_t)b0_ * HH + h_) * SS + s0_) << 6) + d_) = make_float2(v00, v01);
                *(float2*)(C + ((((size_t)b1_ * HH + h_) * SS + s1_) << 6) + d_) = make_float2(v10, v11);
            }
        }
    }
}

// ================= fused attention =================
__global__ __launch_bounds__(256)
void attn_kernel(const float* __restrict__ q, const float* __restrict__ k,
                 const float* __restrict__ v, const int* __restrict__ tok,
                 float* __restrict__ probs, bf16* __restrict__ avh, bf16* __restrict__ avl)
{
    int qb = blockIdx.x;
    int h = blockIdx.y, b = blockIdx.z;
    int tid = threadIdx.x;

    __shared__ float qs[8][64];
    __shared__ float sc[8][512];

    const float* qbase = q + ((((size_t)b * HH + h) * SS + qb * 8) << 6);
    for (int i = tid; i < 8 * 64; i += 256)
        qs[i >> 6][i & 63] = qbase[i];
    __syncthreads();

    const float* kbase = k + (((size_t)b * HH + h) * SS << 6);
    const int* tb = tok + b * SS;

    for (int idx = tid; idx < 8 * 512; idx += 256) {
        int qi = idx >> 9, key = idx & 511;
        const float4* kr4 = (const float4*)(kbase + ((size_t)key << 6));
        float acc = 0.f;
        #pragma unroll
        for (int d4 = 0; d4 < 16; d4++) {
            float4 kv = kr4[d4];
            acc = fmaf(qs[qi][4*d4+0], kv.x, acc);
            acc = fmaf(qs[qi][4*d4+1], kv.y, acc);
            acc = fmaf(qs[qi][4*d4+2], kv.z, acc);
            acc = fmaf(qs[qi][4*d4+3], kv.w, acc);
        }
        sc[qi][key] = (tb[key] == 0) ? -INFINITY : acc * 0.125f;
    }
    __syncthreads();

    int w = tid >> 5, lane = tid & 31;
    {
        float m = -INFINITY;
        for (int key = lane; key < 512; key += 32) m = fmaxf(m, sc[w][key]);
        #pragma unroll
        for (int o = 16; o > 0; o >>= 1) m = fmaxf(m, __shfl_xor_sync(~0u, m, o));
        float sum = 0.f;
        for (int key = lane; key < 512; key += 32) {
            float e = __expf(sc[w][key] - m);
            sc[w][key] = e; sum += e;
        }
        #pragma unroll
        for (int o = 16; o > 0; o >>= 1) sum += __shfl_xor_sync(~0u, sum, o);
        float inv = 1.f / sum;
        float* prow = probs + ((((size_t)b * HH + h) * SS + qb * 8 + w) << 9);
        for (int key = lane; key < 512; key += 32) {
            float p = sc[w][key] * inv;
            sc[w][key] = p;
            prow[key] = p;
        }
    }
    __syncthreads();

    const float* vbase = v + (((size_t)b * HH + h) * SS << 6);
    int d = tid & 63;
    #pragma unroll
    for (int pass = 0; pass < 2; pass++) {
        int qi = (tid >> 6) + pass * 4;
        float acc = 0.f;
        #pragma unroll 4
        for (int key = 0; key < 512; key++)
            acc = fmaf(sc[qi][key], vbase[((size_t)key << 6) + d], acc);
        size_t o = (((size_t)b * SS + qb * 8 + qi) << 10) + (h << 6) + d;
        bf16 hh, ll; split_bf16(acc, hh, ll);
        avh[o] = hh; avl[o] = ll;
    }
}

// ================= layernorm + bf16 split outputs =================
__global__ __launch_bounds__(256)
void ln_kernel(const float* __restrict__ in, float* __restrict__ out,
               bf16* __restrict__ oh, bf16* __restrict__ ol)
{
    int row = blockIdx.x;
    int tid = threadIdx.x;
    const float* r = in + (size_t)row * DD;
    float v0 = r[tid], v1 = r[tid + 256], v2 = r[tid + 512], v3 = r[tid + 768];
    float s = v0 + v1 + v2 + v3;

    __shared__ float sh[32];
    #pragma unroll
    for (int o = 16; o > 0; o >>= 1) s += __shfl_down_sync(~0u, s, o);
    if ((tid & 31) == 0) sh[tid >> 5] = s;
    __syncthreads();
    if (tid < 8) {
        s = sh[tid];
        #pragma unroll
        for (int o = 4; o > 0; o >>= 1) s += __shfl_down_sync(0xffu, s, o);
        if (tid == 0) sh[0] = s;
    }
    __syncthreads();
    float mean = sh[0] * (1.f / 1024.f);
    float d0 = v0 - mean, d1 = v1 - mean, d2 = v2 - mean, d3 = v3 - mean;
    float qv = d0*d0 + d1*d1 + d2*d2 + d3*d3;
    __syncthreads();
    #pragma unroll
    for (int o = 16; o > 0; o >>= 1) qv += __shfl_down_sync(~0u, qv, o);
    if ((tid & 31) == 0) sh[tid >> 5] = qv;
    __syncthreads();
    if (tid < 8) {
        qv = sh[tid];
        #pragma unroll
        for (int o = 4; o > 0; o >>= 1) qv += __shfl_down_sync(0xffu, qv, o);
        if (tid == 0) sh[0] = qv;
    }
    __syncthreads();
    float inv = rsqrtf(sh[0] * (1.f / 1024.f) + 1e-5f);
    size_t base = (size_t)row * DD;
    #pragma unroll
    for (int jj = 0; jj < 4; jj++) {
        float d = (jj == 0 ? d0 : jj == 1 ? d1 : jj == 2 ? d2 : d3);
        float val = d * inv;
        int idx = tid + jj * 256;
        out[base + idx] = val;
        bf16 h, l; split_bf16(val, h, l);
        oh[base + idx] = h; ol[base + idx] = l;
    }
}

__global__ void copy_kernel(const float* __restrict__ src, float* __restrict__ dst, int n)
{
    int i = blockIdx.x * blockDim.x + threadIdx.x;
    if (i < n) dst[i] = src[i];
}

// ================= host driver =================
extern "C" void kernel_launch(void* const* d_in, const int* in_sizes, int n_in,
                              void* d_out, int out_size)
{
    const int*   tok = (const int*)d_in[0];
    const float* we  = (const float*)d_in[1];
    const float* pt  = (const float*)d_in[2];
    const float* Wq  = (const float*)d_in[3];  const float* bq = (const float*)d_in[4];
    const float* Wk  = (const float*)d_in[5];  const float* bk = (const float*)d_in[6];
    const float* Wv  = (const float*)d_in[7];  const float* bv = (const float*)d_in[8];
    const float* Wo  = (const float*)d_in[9];  const float* bo = (const float*)d_in[10];
    const float* W1  = (const float*)d_in[11]; const float* b1 = (const float*)d_in[12];
    const float* W2  = (const float*)d_in[13]; const float* b2 = (const float*)d_in[14];
    float* out = (float*)d_out;

    float *x, *qp, *kp, *vp, *yp, *x1p;
    bf16 *xh, *xl, *avh, *avl, *x1h, *x1l, *ffh, *ffl;
    cudaGetSymbolAddress((void**)&x,   g_x);
    cudaGetSymbolAddress((void**)&xh,  g_xh);  cudaGetSymbolAddress((void**)&xl,  g_xl);
    cudaGetSymbolAddress((void**)&qp,  g_q);
    cudaGetSymbolAddress((void**)&kp,  g_k);
    cudaGetSymbolAddress((void**)&vp,  g_v);
    cudaGetSymbolAddress((void**)&avh, g_avh); cudaGetSymbolAddress((void**)&avl, g_avl);
    cudaGetSymbolAddress((void**)&yp,  g_y);
    cudaGetSymbolAddress((void**)&x1p, g_x1);
    cudaGetSymbolAddress((void**)&x1h, g_x1h); cudaGetSymbolAddress((void**)&x1l, g_x1l);
    cudaGetSymbolAddress((void**)&ffh, g_ffh); cudaGetSymbolAddress((void**)&ffl, g_ffl);

    bf16 *wqh,*wql,*wkh,*wkl,*wvh,*wvl,*woh,*wol,*w1h,*w1l,*w2h,*w2l;
    cudaGetSymbolAddress((void**)&wqh, g_wqT_h); cudaGetSymbolAddress((void**)&wql, g_wqT_l);
    cudaGetSymbolAddress((void**)&wkh, g_wkT_h); cudaGetSymbolAddress((void**)&wkl, g_wkT_l);
    cudaGetSymbolAddress((void**)&wvh, g_wvT_h); cudaGetSymbolAddress((void**)&wvl, g_wvT_l);
    cudaGetSymbolAddress((void**)&woh, g_woT_h); cudaGetSymbolAddress((void**)&wol, g_woT_l);
    cudaGetSymbolAddress((void**)&w1h, g_w1T_h); cudaGetSymbolAddress((void**)&w1l, g_w1T_l);
    cudaGetSymbolAddress((void**)&w2h, g_w2T_h); cudaGetSymbolAddress((void**)&w2l, g_w2T_l);

    cudaFuncSetAttribute(gemm_kernel, cudaFuncAttributeMaxDynamicSharedMemorySize, GSMEM);

    // weight preprocessing
    {
        dim3 gP(DD/32, DD/32, LL);
        wsplit_kernel<<<gP, 256>>>(Wq, wqh, wql, DD, DD);
        wsplit_kernel<<<gP, 256>>>(Wk, wkh, wkl, DD, DD);
        wsplit_kernel<<<gP, 256>>>(Wv, wvh, wvl, DD, DD);
        wsplit_kernel<<<gP, 256>>>(Wo, woh, wol, DD, DD);
        dim3 g1(DFF/32, DD/32, LL);
        wsplit_kernel<<<g1, 256>>>(W1, w1h, w1l, DD, DFF);
        dim3 g2(DD/32, DFF/32, LL);
        wsplit_kernel<<<g2, 256>>>(W2, w2h, w2l, DFF, DD);
    }

    embed_kernel<<<MTOK, 256>>>(tok, we, pt, x, xh, xl);

    dim3 gD (DD  / 128, MTOK / 128);   // (8,16)
    dim3 gFF(DFF / 128, MTOK / 128);   // (32,16)
    dim3 gA (SS / 8, HH, BB);

    const size_t PROJ = (size_t)DD * DD;
    const size_t W1SZ = (size_t)DD * DFF;
    const size_t W2SZ = (size_t)DFF * DD;
    const size_t CORR = (size_t)BB * HH * SS * SS;

    for (int l = 0; l < LL; l++) {
        gemm_kernel<<<gD, 256, GSMEM>>>(xh, xl, wqh + l*PROJ, wql + l*PROJ, bq + l*DD, nullptr, qp, nullptr, nullptr, DD, DD, 3);
        gemm_kernel<<<gD, 256, GSMEM>>>(xh, xl, wkh + l*PROJ, wkl + l*PROJ, bk + l*DD, nullptr, kp, nullptr, nullptr, DD, DD, 3);
        gemm_kernel<<<gD, 256, GSMEM>>>(xh, xl, wvh + l*PROJ, wvl + l*PROJ, bv + l*DD, nullptr, vp, nullptr, nullptr, DD, DD, 3);

        float* probs_l = out + (size_t)MTOK * DD + (size_t)l * CORR;
        attn_kernel<<<gA, 256>>>(qp, kp, vp, tok, probs_l, avh, avl);

        gemm_kernel<<<gD, 256, GSMEM>>>(avh, avl, woh + l*PROJ, wol + l*PROJ, bo + l*DD, x, yp, nullptr, nullptr, DD, DD, 2);
        ln_kernel<<<MTOK, 256>>>(yp, x1p, x1h, x1l);

        gemm_kernel<<<gFF, 256, GSMEM>>>(x1h, x1l, w1h + l*W1SZ, w1l + l*W1SZ, b1 + l*DFF, nullptr, nullptr, ffh, ffl, DD, DFF, 1);
        gemm_kernel<<<gD, 256, GSMEM>>>(ffh, ffl, w2h + l*W2SZ, w2l + l*W2SZ, b2 + l*DD, x1p, yp, nullptr, nullptr, DFF, DD, 2);
        ln_kernel<<<MTOK, 256>>>(yp, x, xh, xl);
    }

    int n = MTOK * DD;
    copy_kernel<<<(n + 255) / 256, 256>>>(x, out, n);
}

// round 4
// speedup vs baseline: 4.7111x; 2.6191x over previous
#include <cuda_runtime.h>
#include <cuda_bf16.h>
#include <math.h>
#include <stdint.h>

// Problem constants
#define BB 4
#define SS 512
#define DD 1024
#define HH 16
#define DHH 64
#define DFF 4096
#define LL 6
#define MTOK (BB*SS)          // 2048 token rows

typedef __nv_bfloat16 bf16;

// ================= device scratch =================
__device__ float g_x  [MTOK*DD];    // residual stream fp32
__device__ bf16  g_xh [MTOK*DD],  g_xl [MTOK*DD];
__device__ float g_qkv[3*MTOK*DD];  // Q,K,V in [3][B,H,S,64]
__device__ bf16  g_avh[MTOK*DD],  g_avl[MTOK*DD];
__device__ float g_y  [MTOK*DD];
__device__ float g_x1 [MTOK*DD];
__device__ bf16  g_x1h[MTOK*DD],  g_x1l[MTOK*DD];
__device__ bf16  g_ffh[MTOK*DFF], g_ffl[MTOK*DFF];

// transposed + bf16-split weights: [N, K] K-major per layer
__device__ bf16 g_wqkvT_h[3*LL*DD*DD], g_wqkvT_l[3*LL*DD*DD];   // [3][L][N][K]
__device__ bf16 g_woT_h[LL*DD*DD],  g_woT_l[LL*DD*DD];
__device__ bf16 g_w1T_h[LL*DD*DFF], g_w1T_l[LL*DD*DFF];
__device__ bf16 g_w2T_h[LL*DFF*DD], g_w2T_l[LL*DFF*DD];
__device__ float g_bqkv[3*LL*DD];

// ================= small helpers =================
__device__ __forceinline__ uint32_t smem_u32(const void* p) {
    uint32_t a;
    asm("{ .reg .u64 t; cvta.to.shared.u64 t, %1; cvt.u32.u64 %0, t; }" : "=r"(a) : "l"(p));
    return a;
}
__device__ __forceinline__ void split_bf16(float v, bf16& h, bf16& l) {
    h = __float2bfloat16_rn(v);
    l = __float2bfloat16_rn(v - __bfloat162float(h));
}

#define CP_ASYNC16(sa, ga) \
    asm volatile("cp.async.cg.shared.global [%0], [%1], 16;" :: "r"(sa), "l"(ga) : "memory")
#define CP_COMMIT() asm volatile("cp.async.commit_group;" ::: "memory")
#define CP_WAIT1()  asm volatile("cp.async.wait_group 1;" ::: "memory")

#define LDSM_X4(r0,r1,r2,r3, addr) \
    asm volatile("ldmatrix.sync.aligned.m8n8.x4.shared.b16 {%0,%1,%2,%3}, [%4];" \
        : "=r"(r0), "=r"(r1), "=r"(r2), "=r"(r3) : "r"(addr))

#define MMA_BF16(d, a, b0, b1) \
    asm volatile("mma.sync.aligned.m16n8k16.row.col.f32.bf16.bf16.f32 " \
        "{%0,%1,%2,%3}, {%4,%5,%6,%7}, {%8,%9}, {%0,%1,%2,%3};" \
        : "+f"((d)[0]), "+f"((d)[1]), "+f"((d)[2]), "+f"((d)[3]) \
        : "r"((a)[0]), "r"((a)[1]), "r"((a)[2]), "r"((a)[3]), "r"(b0), "r"(b1))

// ================= embedding =================
__global__ void embed_kernel(const int* __restrict__ tok,
                             const float* __restrict__ we,
                             const float* __restrict__ pt,
                             float* __restrict__ x,
                             bf16* __restrict__ xh, bf16* __restrict__ xl)
{
    int m = blockIdx.x;
    int t = tok[m];
    const float* wr = we + (size_t)t * DD;
    const float* pr = pt + (size_t)t * DD;
    size_t base = (size_t)m * DD;
    for (int j = threadIdx.x; j < DD; j += blockDim.x) {
        float v = wr[j] + pr[j];
        x[base + j] = v;
        bf16 h, l; split_bf16(v, h, l);
        xh[base + j] = h; xl[base + j] = l;
    }
}

// ========== weight transpose + bf16 split: W[K,N] -> Th/Tl [N,K] ======
__global__ __launch_bounds__(256)
void wsplit_kernel(const float* __restrict__ W, bf16* __restrict__ Th,
                   bf16* __restrict__ Tl, int K, int N)
{
    __shared__ float s[32][33];
    const float* Wb = W + (size_t)blockIdx.z * K * N;
    bf16* Thb = Th + (size_t)blockIdx.z * K * N;
    bf16* Tlb = Tl + (size_t)blockIdx.z * K * N;
    int nb = blockIdx.x * 32, kb = blockIdx.y * 32;
    int tx = threadIdx.x & 31, ty = threadIdx.x >> 5;
    #pragma unroll
    for (int j = 0; j < 4; j++)
        s[ty + 8*j][tx] = Wb[(size_t)(kb + ty + 8*j) * N + nb + tx];
    __syncthreads();
    #pragma unroll
    for (int j = 0; j < 4; j++) {
        float v = s[tx][ty + 8*j];
        bf16 h, l; split_bf16(v, h, l);
        size_t o = (size_t)(nb + ty + 8*j) * K + kb + tx;
        Thb[o] = h; Tlb[o] = l;
    }
}

__global__ void bcat_kernel(const float* __restrict__ a, const float* __restrict__ b,
                            const float* __restrict__ c, float* __restrict__ dst, int n)
{
    int i = blockIdx.x * blockDim.x + threadIdx.x;
    if (i < n) { dst[i] = a[i]; dst[n + i] = b[i]; dst[2*n + i] = c[i]; }
}

// ================= bf16x3 mma.sync GEMM =================
// Tile 128x128, BK=32, 2-stage cp.async pipeline, 2 CTAs/SM.
// mode 0: fp32+bias; 1: relu->bf16 h/l; 2: +bias+Res->fp32; 3: QKV remap.
// blockIdx.z applies zsB/zsBias/zsC offsets (QKV fusion).
#define STAGE_B 32768                  // Ah(8K) Al(8K) Bh(8K) Bl(8K)
#define GSMEM (2*STAGE_B)

__global__ __launch_bounds__(256, 2)
void gemm_kernel(const bf16* __restrict__ Ah, const bf16* __restrict__ Al,
                 const bf16* __restrict__ Bh_, const bf16* __restrict__ Bl_,
                 const float* __restrict__ bias_, const float* __restrict__ Res,
                 float* __restrict__ C_, bf16* __restrict__ Ch, bf16* __restrict__ Cl,
                 int K, int N, int mode, size_t zsB, size_t zsBias, size_t zsC)
{
    extern __shared__ char smem[];
    const uint32_t sb = smem_u32(smem);
    const int tid = threadIdx.x;
    const int lane = tid & 31, wid = tid >> 5;
    const int warp_m = wid & 3, warp_n = wid >> 2;
    const int m0 = blockIdx.y * 128, n0 = blockIdx.x * 128;

    const bf16* Bh = Bh_ + blockIdx.z * zsB;
    const bf16* Bl = Bl_ + blockIdx.z * zsB;
    const float* bias = bias_ + blockIdx.z * zsBias;
    float* C = C_ + blockIdx.z * zsC;

    int lrow0 = tid >> 2, lkg0 = tid & 3;
    int lrow1 = (tid + 256) >> 2;
    uint32_t soff0 = (uint32_t)(lrow0 * 64 + ((lkg0 ^ ((lrow0 >> 1) & 3)) << 4));
    uint32_t soff1 = (uint32_t)(lrow1 * 64 + ((lkg0 ^ ((lrow1 >> 1) & 3)) << 4));

    const bf16* gAh = Ah + (size_t)(m0 + lrow0) * K + lkg0 * 8;
    const bf16* gAl = Al + (size_t)(m0 + lrow0) * K + lkg0 * 8;
    const bf16* gBh = Bh + (size_t)(n0 + lrow0) * K + lkg0 * 8;
    const bf16* gBl = Bl + (size_t)(n0 + lrow0) * K + lkg0 * 8;
    const bf16* gAh1 = Ah + (size_t)(m0 + lrow1) * K + lkg0 * 8;
    const bf16* gAl1 = Al + (size_t)(m0 + lrow1) * K + lkg0 * 8;
    const bf16* gBh1 = Bh + (size_t)(n0 + lrow1) * K + lkg0 * 8;
    const bf16* gBl1 = Bl + (size_t)(n0 + lrow1) * K + lkg0 * 8;

    int matA = lane >> 3;
    int arow_local = ((matA & 1) << 3) + (lane & 7);
    int akgbit = matA >> 1;
    uint32_t offA[2][2];
    #pragma unroll
    for (int mt = 0; mt < 2; mt++) {
        int row = warp_m * 32 + mt * 16 + arow_local;
        int swz = (row >> 1) & 3;
        #pragma unroll
        for (int ks = 0; ks < 2; ks++)
            offA[mt][ks] = (uint32_t)(row * 64 + (((ks * 2 + akgbit) ^ swz) << 4));
    }
    int brow_local = ((matA >> 1) << 3) + (lane & 7);
    int bkgbit = lane >> 3 & 1;
    uint32_t offB[4][2];
    #pragma unroll
    for (int np = 0; np < 4; np++) {
        int row = warp_n * 64 + np * 16 + brow_local;
        int swz = (row >> 1) & 3;
        #pragma unroll
        for (int ks = 0; ks < 2; ks++)
            offB[np][ks] = (uint32_t)(row * 64 + (((ks * 2 + bkgbit) ^ swz) << 4));
    }

    float acc[2][8][4];
    #pragma unroll
    for (int i = 0; i < 2; i++)
        #pragma unroll
        for (int j = 0; j < 8; j++)
            #pragma unroll
            for (int qq = 0; qq < 4; qq++) acc[i][j][qq] = 0.f;

    const int NC = K >> 5;

    auto load_stage = [&](int stage, int chunk) {
        uint32_t base = sb + stage * STAGE_B;
        size_t gk = (size_t)(chunk << 5);
        CP_ASYNC16(base           + soff0, gAh  + gk);
        CP_ASYNC16(base +  8192u  + soff0, gAl  + gk);
        CP_ASYNC16(base + 16384u  + soff0, gBh  + gk);
        CP_ASYNC16(base + 24576u  + soff0, gBl  + gk);
        CP_ASYNC16(base           + soff1, gAh1 + gk);
        CP_ASYNC16(base +  8192u  + soff1, gAl1 + gk);
        CP_ASYNC16(base + 16384u  + soff1, gBh1 + gk);
        CP_ASYNC16(base + 24576u  + soff1, gBl1 + gk);
    };

    load_stage(0, 0); CP_COMMIT();
    if (NC > 1) load_stage(1, 1);
    CP_COMMIT();

    for (int i = 0; i < NC; i++) {
        CP_WAIT1();
        __syncthreads();

        uint32_t base = sb + (i & 1) * STAGE_B;
        uint32_t sAh = base, sAl = base + 8192u, sBh = base + 16384u, sBl = base + 24576u;

        #pragma unroll
        for (int ks = 0; ks < 2; ks++) {
            uint32_t ah[2][4], al[2][4];
            #pragma unroll
            for (int mt = 0; mt < 2; mt++) {
                LDSM_X4(ah[mt][0], ah[mt][1], ah[mt][2], ah[mt][3], sAh + offA[mt][ks]);
                LDSM_X4(al[mt][0], al[mt][1], al[mt][2], al[mt][3], sAl + offA[mt][ks]);
            }
            #pragma unroll
            for (int np = 0; np < 4; np++) {
                uint32_t bh[4], bl[4];
                LDSM_X4(bh[0], bh[1], bh[2], bh[3], sBh + offB[np][ks]);
                LDSM_X4(bl[0], bl[1], bl[2], bl[3], sBl + offB[np][ks]);
                #pragma unroll
                for (int mt = 0; mt < 2; mt++) {
                    MMA_BF16(acc[mt][np*2+0], ah[mt], bh[0], bh[1]);
                    MMA_BF16(acc[mt][np*2+0], al[mt], bh[0], bh[1]);
                    MMA_BF16(acc[mt][np*2+0], ah[mt], bl[0], bl[1]);
                    MMA_BF16(acc[mt][np*2+1], ah[mt], bh[2], bh[3]);
                    MMA_BF16(acc[mt][np*2+1], al[mt], bh[2], bh[3]);
                    MMA_BF16(acc[mt][np*2+1], ah[mt], bl[2], bl[3]);
                }
            }
        }
        __syncthreads();
        if (i + 2 < NC) { load_stage(i & 1, i + 2); }
        CP_COMMIT();
    }

    // -------- epilogue --------
    #pragma unroll
    for (int mt = 0; mt < 2; mt++) {
        int r0 = m0 + warp_m * 32 + mt * 16 + (lane >> 2);
        int r1 = r0 + 8;
        #pragma unroll
        for (int nt = 0; nt < 8; nt++) {
            int c = n0 + warp_n * 64 + nt * 8 + ((lane & 3) << 1);
            float2 bv = *(const float2*)(bias + c);
            float v00 = acc[mt][nt][0] + bv.x, v01 = acc[mt][nt][1] + bv.y;
            float v10 = acc[mt][nt][2] + bv.x, v11 = acc[mt][nt][3] + bv.y;
            if (mode == 0) {
                *(float2*)(C + (size_t)r0 * N + c) = make_float2(v00, v01);
                *(float2*)(C + (size_t)r1 * N + c) = make_float2(v10, v11);
            } else if (mode == 1) {
                v00 = fmaxf(v00, 0.f); v01 = fmaxf(v01, 0.f);
                v10 = fmaxf(v10, 0.f); v11 = fmaxf(v11, 0.f);
                bf16 h0,l0,h1,l1,h2,l2,h3,l3;
                split_bf16(v00,h0,l0); split_bf16(v01,h1,l1);
                split_bf16(v10,h2,l2); split_bf16(v11,h3,l3);
                __nv_bfloat162 ph0; ph0.x = h0; ph0.y = h1;
                __nv_bfloat162 pl0; pl0.x = l0; pl0.y = l1;
                __nv_bfloat162 ph1; ph1.x = h2; ph1.y = h3;
                __nv_bfloat162 pl1; pl1.x = l2; pl1.y = l3;
                *(__nv_bfloat162*)(Ch + (size_t)r0 * N + c) = ph0;
                *(__nv_bfloat162*)(Cl + (size_t)r0 * N + c) = pl0;
                *(__nv_bfloat162*)(Ch + (size_t)r1 * N + c) = ph1;
                *(__nv_bfloat162*)(Cl + (size_t)r1 * N + c) = pl1;
            } else if (mode == 2) {
                float2 q0 = *(const float2*)(Res + (size_t)r0 * N + c);
                float2 q1 = *(const float2*)(Res + (size_t)r1 * N + c);
                *(float2*)(C + (size_t)r0 * N + c) = make_float2(v00 + q0.x, v01 + q0.y);
                *(float2*)(C + (size_t)r1 * N + c) = make_float2(v10 + q1.x, v11 + q1.y);
            } else {
                int b0_ = r0 >> 9, s0_ = r0 & 511;
                int b1_ = r1 >> 9, s1_ = r1 & 511;
                int h_ = c >> 6, d_ = c & 63;
                *(float2*)(C + ((((size_t)b0_ * HH + h_) * SS + s0_) << 6) + d_) = make_float2(v00, v01);
                *(float2*)(C + ((((size_t)b1_ * HH + h_) * SS + s1_) << 6) + d_) = make_float2(v10, v11);
            }
        }
    }
}

// ================= fused attention: 32 queries/block =================
// smem layout (floats): qsT[64][36] | sc[32][513] | kv[64][68]
#define A_QST 0
#define A_SC  (64*36)
#define A_KV  (64*36 + 32*513)
#define A_TOT (64*36 + 32*513 + 64*68)   // 23072 floats = 92288 B

__global__ __launch_bounds__(256, 2)
void attn_kernel(const float* __restrict__ q, const float* __restrict__ k,
                 const float* __restrict__ v, const int* __restrict__ tok,
                 float* __restrict__ probs, bf16* __restrict__ avh, bf16* __restrict__ avl)
{
    extern __shared__ float sm[];
    float* qsT = sm + A_QST;
    float* sc  = sm + A_SC;
    float* kv  = sm + A_KV;
    int qb = blockIdx.x, h = blockIdx.y, b = blockIdx.z;
    int tid = threadIdx.x;

    const float* qbase = q + ((((size_t)b * HH + h) * SS + qb * 32) << 6);
    #pragma unroll
    for (int t = 0; t < 2; t++) {
        int j = tid + 256 * t;            // 512 float4 groups
        int row = j >> 4, c4 = j & 15;
        float4 qv = *(const float4*)(qbase + row * 64 + c4 * 4);
        qsT[(c4*4+0)*36 + row] = qv.x;
        qsT[(c4*4+1)*36 + row] = qv.y;
        qsT[(c4*4+2)*36 + row] = qv.z;
        qsT[(c4*4+3)*36 + row] = qv.w;
    }
    __syncthreads();

    const float* kbase = k + (((size_t)b * HH + h) * SS << 6);
    const int* tb = tok + b * SS;
    const int qgrp = tid & 7, kgrp = tid >> 3;

    // ---- scores: 8 chunks of 64 keys ----
    for (int ch = 0; ch < 8; ch++) {
        #pragma unroll
        for (int t = 0; t < 4; t++) {
            int j = tid + 256 * t;        // 1024 float4
            int row = j >> 4, c4 = j & 15;
            float4 kvv = *(const float4*)(kbase + (size_t)(ch*64 + row) * 64 + c4 * 4);
            *(float4*)(kv + row * 68 + c4 * 4) = kvv;
        }
        __syncthreads();
        float acc[4][2] = {};
        #pragma unroll
        for (int d = 0; d < 64; d++) {
            float4 qv = *(const float4*)(qsT + d * 36 + qgrp * 4);
            float k0 = kv[(kgrp*2+0)*68 + d];
            float k1 = kv[(kgrp*2+1)*68 + d];
            acc[0][0] = fmaf(qv.x, k0, acc[0][0]); acc[0][1] = fmaf(qv.x, k1, acc[0][1]);
            acc[1][0] = fmaf(qv.y, k0, acc[1][0]); acc[1][1] = fmaf(qv.y, k1, acc[1][1]);
            acc[2][0] = fmaf(qv.z, k0, acc[2][0]); acc[2][1] = fmaf(qv.z, k1, acc[2][1]);
            acc[3][0] = fmaf(qv.w, k0, acc[3][0]); acc[3][1] = fmaf(qv.w, k1, acc[3][1]);
        }
        #pragma unroll
        for (int j = 0; j < 2; j++) {
            int key = ch * 64 + kgrp * 2 + j;
            bool msk = (tb[key] == 0);
            #pragma unroll
            for (int i = 0; i < 4; i++)
                sc[(qgrp*4+i)*513 + key] = msk ? -INFINITY : acc[i][j] * 0.125f;
        }
        __syncthreads();
    }

    // ---- softmax: 8 warps x 4 rows ----
    int w = tid >> 5, lane = tid & 31;
    #pragma unroll 1
    for (int rr = 0; rr < 4; rr++) {
        int row = w * 4 + rr;
        float* srow = sc + row * 513;
        float m = -INFINITY;
        for (int j = lane; j < 512; j += 32) m = fmaxf(m, srow[j]);
        #pragma unroll
        for (int o = 16; o > 0; o >>= 1) m = fmaxf(m, __shfl_xor_sync(~0u, m, o));
        float sum = 0.f;
        for (int j = lane; j < 512; j += 32) {
            float e = __expf(srow[j] - m);
            srow[j] = e; sum += e;
        }
        #pragma unroll
        for (int o = 16; o > 0; o >>= 1) sum += __shfl_xor_sync(~0u, sum, o);
        float inv = 1.f / sum;
        float* prow = probs + ((((size_t)b * HH + h) * SS + qb * 32 + row) << 9);
        for (int j = lane; j < 512; j += 32) {
            float p = srow[j] * inv;
            srow[j] = p;
            prow[j] = p;
        }
    }
    __syncthreads();

    // ---- AV: 8 chunks of 64 keys; thread owns q=tid&31, d-group=tid>>5 ----
    const float* vbase = v + (((size_t)b * HH + h) * SS << 6);
    int ql = tid & 31, dg = tid >> 5;
    float a8[8] = {};
    for (int ch = 0; ch < 8; ch++) {
        #pragma unroll
        for (int t = 0; t < 4; t++) {
            int j = tid + 256 * t;
            int row = j >> 4, c4 = j & 15;
            float4 vv = *(const float4*)(vbase + (size_t)(ch*64 + row) * 64 + c4 * 4);
            *(float4*)(kv + row * 68 + c4 * 4) = vv;
        }
        __syncthreads();
        const float* srow = sc + ql * 513 + ch * 64;
        #pragma unroll 4
        for (int kk = 0; kk < 64; kk++) {
            float s = srow[kk];
            float4 v0 = *(const float4*)(kv + kk * 68 + dg * 8);
            float4 v1 = *(const float4*)(kv + kk * 68 + dg * 8 + 4);
            a8[0] = fmaf(s, v0.x, a8[0]); a8[1] = fmaf(s, v0.y, a8[1]);
            a8[2] = fmaf(s, v0.z, a8[2]); a8[3] = fmaf(s, v0.w, a8[3]);
            a8[4] = fmaf(s, v1.x, a8[4]); a8[5] = fmaf(s, v1.y, a8[5]);
            a8[6] = fmaf(s, v1.z, a8[6]); a8[7] = fmaf(s, v1.w, a8[7]);
        }
        __syncthreads();
    }
    // write av [B,S,H*64] split
    size_t o = ((size_t)(b * SS + qb * 32 + ql) << 10) + h * 64 + dg * 8;
    uint32_t ph[4], pl[4];
    #pragma unroll
    for (int i = 0; i < 4; i++) {
        bf16 h0, l0, h1, l1;
        split_bf16(a8[2*i], h0, l0);
        split_bf16(a8[2*i+1], h1, l1);
        ph[i] = ((uint32_t)__bfloat16_as_ushort(h1) << 16) | __bfloat16_as_ushort(h0);
        pl[i] = ((uint32_t)__bfloat16_as_ushort(l1) << 16) | __bfloat16_as_ushort(l0);
    }
    *(uint4*)(avh + o) = make_uint4(ph[0], ph[1], ph[2], ph[3]);
    *(uint4*)(avl + o) = make_uint4(pl[0], pl[1], pl[2], pl[3]);
}

// ================= layernorm + bf16 split =================
__global__ __launch_bounds__(256)
void ln_kernel(const float* __restrict__ in, float* __restrict__ out,
               bf16* __restrict__ oh, bf16* __restrict__ ol)
{
    int row = blockIdx.x;
    int tid = threadIdx.x;
    const float* r = in + (size_t)row * DD;
    float v0 = r[tid], v1 = r[tid + 256], v2 = r[tid + 512], v3 = r[tid + 768];
    float s = v0 + v1 + v2 + v3;

    __shared__ float sh[32];
    #pragma unroll
    for (int o = 16; o > 0; o >>= 1) s += __shfl_down_sync(~0u, s, o);
    if ((tid & 31) == 0) sh[tid >> 5] = s;
    __syncthreads();
    if (tid < 8) {
        s = sh[tid];
        #pragma unroll
        for (int o = 4; o > 0; o >>= 1) s += __shfl_down_sync(0xffu, s, o);
        if (tid == 0) sh[0] = s;
    }
    __syncthreads();
    float mean = sh[0] * (1.f / 1024.f);
    float d0 = v0 - mean, d1 = v1 - mean, d2 = v2 - mean, d3 = v3 - mean;
    float qv = d0*d0 + d1*d1 + d2*d2 + d3*d3;
    __syncthreads();
    #pragma unroll
    for (int o = 16; o > 0; o >>= 1) qv += __shfl_down_sync(~0u, qv, o);
    if ((tid & 31) == 0) sh[tid >> 5] = qv;
    __syncthreads();
    if (tid < 8) {
        qv = sh[tid];
        #pragma unroll
        for (int o = 4; o > 0; o >>= 1) qv += __shfl_down_sync(0xffu, qv, o);
        if (tid == 0) sh[0] = qv;
    }
    __syncthreads();
    float inv = rsqrtf(sh[0] * (1.f / 1024.f) + 1e-5f);
    size_t base = (size_t)row * DD;
    #pragma unroll
    for (int jj = 0; jj < 4; jj++) {
        float d = (jj == 0 ? d0 : jj == 1 ? d1 : jj == 2 ? d2 : d3);
        float val = d * inv;
        int idx = tid + jj * 256;
        out[base + idx] = val;
        bf16 h, l; split_bf16(val, h, l);
        oh[base + idx] = h; ol[base + idx] = l;
    }
}

__global__ void copy_kernel(const float4* __restrict__ src, float4* __restrict__ dst, int n4)
{
    int i = blockIdx.x * blockDim.x + threadIdx.x;
    if (i < n4) dst[i] = src[i];
}

// ================= host driver =================
extern "C" void kernel_launch(void* const* d_in, const int* in_sizes, int n_in,
                              void* d_out, int out_size)
{
    const int*   tok = (const int*)d_in[0];
    const float* we  = (const float*)d_in[1];
    const float* pt  = (const float*)d_in[2];
    const float* Wq  = (const float*)d_in[3];  const float* bq = (const float*)d_in[4];
    const float* Wk  = (const float*)d_in[5];  const float* bk = (const float*)d_in[6];
    const float* Wv  = (const float*)d_in[7];  const float* bv = (const float*)d_in[8];
    const float* Wo  = (const float*)d_in[9];  const float* bo = (const float*)d_in[10];
    const float* W1  = (const float*)d_in[11]; const float* b1 = (const float*)d_in[12];
    const float* W2  = (const float*)d_in[13]; const float* b2 = (const float*)d_in[14];
    float* out = (float*)d_out;

    float *x, *qkv, *yp, *x1p, *bqkv;
    bf16 *xh, *xl, *avh, *avl, *x1h, *x1l, *ffh, *ffl;
    cudaGetSymbolAddress((void**)&x,   g_x);
    cudaGetSymbolAddress((void**)&xh,  g_xh);  cudaGetSymbolAddress((void**)&xl,  g_xl);
    cudaGetSymbolAddress((void**)&qkv, g_qkv);
    cudaGetSymbolAddress((void**)&avh, g_avh); cudaGetSymbolAddress((void**)&avl, g_avl);
    cudaGetSymbolAddress((void**)&yp,  g_y);
    cudaGetSymbolAddress((void**)&x1p, g_x1);
    cudaGetSymbolAddress((void**)&x1h, g_x1h); cudaGetSymbolAddress((void**)&x1l, g_x1l);
    cudaGetSymbolAddress((void**)&ffh, g_ffh); cudaGetSymbolAddress((void**)&ffl, g_ffl);
    cudaGetSymbolAddress((void**)&bqkv, g_bqkv);

    bf16 *wqkvh, *wqkvl, *woh, *wol, *w1h, *w1l, *w2h, *w2l;
    cudaGetSymbolAddress((void**)&wqkvh, g_wqkvT_h); cudaGetSymbolAddress((void**)&wqkvl, g_wqkvT_l);
    cudaGetSymbolAddress((void**)&woh, g_woT_h); cudaGetSymbolAddress((void**)&wol, g_woT_l);
    cudaGetSymbolAddress((void**)&w1h, g_w1T_h); cudaGetSymbolAddress((void**)&w1l, g_w1T_l);
    cudaGetSymbolAddress((void**)&w2h, g_w2T_h); cudaGetSymbolAddress((void**)&w2l, g_w2T_l);

    cudaFuncSetAttribute(gemm_kernel, cudaFuncAttributeMaxDynamicSharedMemorySize, GSMEM);
    cudaFuncSetAttribute(attn_kernel, cudaFuncAttributeMaxDynamicSharedMemorySize, A_TOT * 4);

    // weight preprocessing
    {
        const size_t WQKV = (size_t)LL * DD * DD;
        dim3 gP(DD/32, DD/32, LL);
        wsplit_kernel<<<gP, 256>>>(Wq, wqkvh,          wqkvl,          DD, DD);
        wsplit_kernel<<<gP, 256>>>(Wk, wqkvh + WQKV,   wqkvl + WQKV,   DD, DD);
        wsplit_kernel<<<gP, 256>>>(Wv, wqkvh + 2*WQKV, wqkvl + 2*WQKV, DD, DD);
        wsplit_kernel<<<gP, 256>>>(Wo, woh, wol, DD, DD);
        dim3 g1(DFF/32, DD/32, LL);
        wsplit_kernel<<<g1, 256>>>(W1, w1h, w1l, DD, DFF);
        dim3 g2(DD/32, DFF/32, LL);
        wsplit_kernel<<<g2, 256>>>(W2, w2h, w2l, DFF, DD);
        bcat_kernel<<<(LL*DD + 255)/256, 256>>>(bq, bk, bv, bqkv, LL*DD);
    }

    embed_kernel<<<MTOK, 256>>>(tok, we, pt, x, xh, xl);

    dim3 gQKV(DD / 128, MTOK / 128, 3);   // (8,16,3)
    dim3 gD  (DD / 128, MTOK / 128);      // (8,16)
    dim3 gFF (DFF / 128, MTOK / 128);     // (32,16)
    dim3 gA  (SS / 32, HH, BB);           // (16,16,4)

    const size_t PROJ = (size_t)DD * DD;
    const size_t WQKV = (size_t)LL * DD * DD;
    const size_t W1SZ = (size_t)DD * DFF;
    const size_t W2SZ = (size_t)DFF * DD;
    const size_t CORR = (size_t)BB * HH * SS * SS;
    const size_t QKVS = (size_t)MTOK * DD;

    float* qp = qkv;
    float* kp = qkv + QKVS;
    float* vp = qkv + 2*QKVS;

    for (int l = 0; l < LL; l++) {
        gemm_kernel<<<gQKV, 256, GSMEM>>>(xh, xl, wqkvh + l*PROJ, wqkvl + l*PROJ,
                                          bqkv + l*DD, nullptr, qkv, nullptr, nullptr,
                                          DD, DD, 3, WQKV, (size_t)LL*DD, QKVS);

        float* probs_l = out + (size_t)MTOK * DD + (size_t)l * CORR;
        attn_kernel<<<gA, 256, A_TOT*4>>>(qp, kp, vp, tok, probs_l, avh, avl);

        gemm_kernel<<<gD, 256, GSMEM>>>(avh, avl, woh + l*PROJ, wol + l*PROJ, bo + l*DD,
                                        x, yp, nullptr, nullptr, DD, DD, 2, 0, 0, 0);
        ln_kernel<<<MTOK, 256>>>(yp, x1p, x1h, x1l);

        gemm_kernel<<<gFF, 256, GSMEM>>>(x1h, x1l, w1h + l*W1SZ, w1l + l*W1SZ, b1 + l*DFF,
                                         nullptr, nullptr, ffh, ffl, DD, DFF, 1, 0, 0, 0);
        gemm_kernel<<<gD, 256, GSMEM>>>(ffh, ffl, w2h + l*W2SZ, w2l + l*W2SZ, b2 + l*DD,
                                        x1p, yp, nullptr, nullptr, DFF, DD, 2, 0, 0, 0);
        ln_kernel<<<MTOK, 256>>>(yp, x, xh, xl);
    }

    int n4 = MTOK * DD / 4;
    copy_kernel<<<(n4 + 255) / 256, 256>>>((const float4*)x, (float4*)out, n4);
}